// round 1
// baseline (speedup 1.0000x reference)
#include <cuda_runtime.h>

// EdgeNet: out[e] = sigmoid( tanh( [Ro^T X ; Ri^T X][e] @ W1 + b1 ) @ W2 + b2 )
// N_NODES=8192, N_EDGES=32768. Ri/Ro are dense [N, E] fp32 (1 GB each) ->
// kernel is HBM-bound streaming those two matrices exactly once.

#define N_NODES 8192
#define N_EDGES 32768
#define EPB     256     // edges per block (1 edge per thread)
#define NTHREADS 256
#define NCHUNK  2048    // X rows staged in shared memory per chunk (32 KB)
#define NHID    100

__global__ __launch_bounds__(NTHREADS, 1)
void edgenet_fused_kernel(const float* __restrict__ X,
                          const float* __restrict__ Ri,
                          const float* __restrict__ Ro,
                          const float* __restrict__ W1,
                          const float* __restrict__ b1,
                          const float* __restrict__ W2,
                          const float* __restrict__ b2,
                          float* __restrict__ out)
{
    __shared__ float4 sX[NCHUNK];                    // 32 KB
    __shared__ __align__(16) float sW1t[NHID][8];    // W1 transposed: [j][k]
    __shared__ float sb1[NHID];
    __shared__ float sW2[NHID];

    const int tid = threadIdx.x;
    const int e   = blockIdx.x * EPB + tid;

    // Stage MLP weights (tiny)
    for (int i = tid; i < 8 * NHID; i += NTHREADS) {
        int k = i / NHID, j = i % NHID;   // W1 is [8,100] row-major
        sW1t[j][k] = W1[i];
    }
    for (int i = tid; i < NHID; i += NTHREADS) {
        sb1[i] = b1[i];
        sW2[i] = W2[i];
    }

    float4 ao = make_float4(0.f, 0.f, 0.f, 0.f);   // bo accumulator (Ro)
    float4 ai = make_float4(0.f, 0.f, 0.f, 0.f);   // bi accumulator (Ri)

    const float4* __restrict__ X4 = (const float4*)X;

    for (int c0 = 0; c0 < N_NODES; c0 += NCHUNK) {
        __syncthreads();
        // Stage X chunk: uniform-broadcast reads later, conflict-free
        for (int i = tid; i < NCHUNK; i += NTHREADS)
            sX[i] = X4[c0 + i];
        __syncthreads();

        const float* __restrict__ ro_p = Ro + (size_t)c0 * N_EDGES + e;
        const float* __restrict__ ri_p = Ri + (size_t)c0 * N_EDGES + e;

        #pragma unroll 8
        for (int n = 0; n < NCHUNK; ++n) {
            float ro = __ldg(ro_p); ro_p += N_EDGES;   // coalesced: warp reads 128B row segment
            float ri = __ldg(ri_p); ri_p += N_EDGES;
            float4 x = sX[n];                          // broadcast LDS
            ao.x = fmaf(ro, x.x, ao.x);
            ao.y = fmaf(ro, x.y, ao.y);
            ao.z = fmaf(ro, x.z, ao.z);
            ao.w = fmaf(ro, x.w, ao.w);
            ai.x = fmaf(ri, x.x, ai.x);
            ai.y = fmaf(ri, x.y, ai.y);
            ai.z = fmaf(ri, x.z, ai.z);
            ai.w = fmaf(ri, x.w, ai.w);
        }
    }

    // Fused MLP: h = tanh(B @ W1 + b1); out = sigmoid(h @ W2 + b2)
    float acc = b2[0];
    #pragma unroll 4
    for (int j = 0; j < NHID; ++j) {
        const float4 w0 = *(const float4*)&sW1t[j][0];   // rows 0..3 -> bo
        const float4 w1 = *(const float4*)&sW1t[j][4];   // rows 4..7 -> bi
        float s = sb1[j];
        s = fmaf(ao.x, w0.x, s);
        s = fmaf(ao.y, w0.y, s);
        s = fmaf(ao.z, w0.z, s);
        s = fmaf(ao.w, w0.w, s);
        s = fmaf(ai.x, w1.x, s);
        s = fmaf(ai.y, w1.y, s);
        s = fmaf(ai.z, w1.z, s);
        s = fmaf(ai.w, w1.w, s);
        acc = fmaf(tanhf(s), sW2[j], acc);
    }
    out[e] = 1.0f / (1.0f + expf(-acc));
}

extern "C" void kernel_launch(void* const* d_in, const int* in_sizes, int n_in,
                              void* d_out, int out_size)
{
    // metadata order: X, Ri, Ro, W1, b1, W2, b2
    const float* X  = (const float*)d_in[0];
    const float* Ri = (const float*)d_in[1];
    const float* Ro = (const float*)d_in[2];
    const float* W1 = (const float*)d_in[3];
    const float* b1 = (const float*)d_in[4];
    const float* W2 = (const float*)d_in[5];
    const float* b2 = (const float*)d_in[6];
    float* out = (float*)d_out;

    dim3 grid(N_EDGES / EPB);   // 128 blocks
    dim3 block(NTHREADS);       // 256 threads
    edgenet_fused_kernel<<<grid, block>>>(X, Ri, Ro, W1, b1, W2, b2, out);
}

// round 2
// speedup vs baseline: 2.3765x; 2.3765x over previous
#include <cuda_runtime.h>

// EdgeNet fused, v2: node-split + float4 edge loads for memory-level parallelism.
// Phase 1: 512 blocks (32 edge-groups x 16 node-segments) stream Ro/Ri with
//          LDG.128, accumulate per-edge partial [bo;bi] into 16MB scratch.
// Phase 2: sum 16 partials per edge + fused MLP (8->100 tanh -> 1 sigmoid).

#define N_NODES 8192
#define N_EDGES 32768
#define NTHREADS 256
#define S_SEG   16
#define NODES_PER_SEG (N_NODES / S_SEG)      // 512
#define E4      (N_EDGES / 4)                // 8192 float4 columns
#define EGRPS   (E4 / NTHREADS)              // 32 edge-group blocks
#define NHID    100

// Per (segment, edge): bo(float4), bi(float4).  16*32768*2*16B = 16 MB.
__device__ float4 g_partial[(size_t)S_SEG * N_EDGES * 2];

__device__ __forceinline__ void fma4(float4& a, float s, const float4& x) {
    a.x = fmaf(s, x.x, a.x);
    a.y = fmaf(s, x.y, a.y);
    a.z = fmaf(s, x.z, a.z);
    a.w = fmaf(s, x.w, a.w);
}

__global__ __launch_bounds__(NTHREADS)
void edgenet_accum_kernel(const float* __restrict__ X,
                          const float* __restrict__ Ri,
                          const float* __restrict__ Ro)
{
    __shared__ float4 sX[NODES_PER_SEG];   // 8 KB

    const int tid = threadIdx.x;
    const int seg = blockIdx.y;
    const int n0  = seg * NODES_PER_SEG;

    const float4* __restrict__ X4 = (const float4*)X;
    for (int i = tid; i < NODES_PER_SEG; i += NTHREADS)
        sX[i] = X4[n0 + i];
    __syncthreads();

    const int e4 = blockIdx.x * NTHREADS + tid;          // this thread's float4 column
    const float4* __restrict__ ro_p = (const float4*)Ro + (size_t)n0 * E4 + e4;
    const float4* __restrict__ ri_p = (const float4*)Ri + (size_t)n0 * E4 + e4;

    float4 ao0 = {0,0,0,0}, ao1 = {0,0,0,0}, ao2 = {0,0,0,0}, ao3 = {0,0,0,0};
    float4 ai0 = {0,0,0,0}, ai1 = {0,0,0,0}, ai2 = {0,0,0,0}, ai3 = {0,0,0,0};

    #pragma unroll 4
    for (int n = 0; n < NODES_PER_SEG; ++n) {
        const float4 ro = ro_p[(size_t)n * E4];   // 4 edges' Ro values (LDG.128)
        const float4 ri = ri_p[(size_t)n * E4];
        const float4 x  = sX[n];                  // broadcast
        fma4(ao0, ro.x, x);  fma4(ao1, ro.y, x);
        fma4(ao2, ro.z, x);  fma4(ao3, ro.w, x);
        fma4(ai0, ri.x, x);  fma4(ai1, ri.y, x);
        fma4(ai2, ri.z, x);  fma4(ai3, ri.w, x);
    }

    // Write partials: edge e = e4*4+q -> slot (seg*E + e)*2 + {0:bo, 1:bi}
    float4* __restrict__ dst = &g_partial[((size_t)seg * N_EDGES + (size_t)e4 * 4) * 2];
    dst[0] = ao0;  dst[1] = ai0;
    dst[2] = ao1;  dst[3] = ai1;
    dst[4] = ao2;  dst[5] = ai2;
    dst[6] = ao3;  dst[7] = ai3;
}

__device__ __forceinline__ void add4(float4& a, const float4& b) {
    a.x += b.x; a.y += b.y; a.z += b.z; a.w += b.w;
}

__global__ __launch_bounds__(NTHREADS)
void edgenet_mlp_kernel(const float* __restrict__ W1,
                        const float* __restrict__ b1,
                        const float* __restrict__ W2,
                        const float* __restrict__ b2,
                        float* __restrict__ out)
{
    __shared__ __align__(16) float sW1t[NHID][8];   // W1 transposed [j][k]
    __shared__ float sb1[NHID];
    __shared__ float sW2[NHID];

    const int tid = threadIdx.x;
    for (int i = tid; i < 8 * NHID; i += NTHREADS) {
        int k = i / NHID, j = i % NHID;             // W1 is [8,100] row-major
        sW1t[j][k] = W1[i];
    }
    for (int i = tid; i < NHID; i += NTHREADS) {
        sb1[i] = b1[i];
        sW2[i] = W2[i];
    }
    __syncthreads();

    const int e = blockIdx.x * NTHREADS + tid;

    float4 ao = {0,0,0,0}, ai = {0,0,0,0};
    #pragma unroll
    for (int seg = 0; seg < S_SEG; ++seg) {
        const float4* p = &g_partial[((size_t)seg * N_EDGES + e) * 2];
        add4(ao, p[0]);
        add4(ai, p[1]);
    }

    float acc = b2[0];
    #pragma unroll 4
    for (int j = 0; j < NHID; ++j) {
        const float4 w0 = *(const float4*)&sW1t[j][0];
        const float4 w1 = *(const float4*)&sW1t[j][4];
        float s = sb1[j];
        s = fmaf(ao.x, w0.x, s);
        s = fmaf(ao.y, w0.y, s);
        s = fmaf(ao.z, w0.z, s);
        s = fmaf(ao.w, w0.w, s);
        s = fmaf(ai.x, w1.x, s);
        s = fmaf(ai.y, w1.y, s);
        s = fmaf(ai.z, w1.z, s);
        s = fmaf(ai.w, w1.w, s);
        acc = fmaf(tanhf(s), sW2[j], acc);
    }
    out[e] = 1.0f / (1.0f + expf(-acc));
}

extern "C" void kernel_launch(void* const* d_in, const int* in_sizes, int n_in,
                              void* d_out, int out_size)
{
    // metadata order: X, Ri, Ro, W1, b1, W2, b2
    const float* X  = (const float*)d_in[0];
    const float* Ri = (const float*)d_in[1];
    const float* Ro = (const float*)d_in[2];
    const float* W1 = (const float*)d_in[3];
    const float* b1 = (const float*)d_in[4];
    const float* W2 = (const float*)d_in[5];
    const float* b2 = (const float*)d_in[6];
    float* out = (float*)d_out;

    dim3 grid1(EGRPS, S_SEG);              // 32 x 16 = 512 blocks
    edgenet_accum_kernel<<<grid1, NTHREADS>>>(X, Ri, Ro);

    dim3 grid2(N_EDGES / NTHREADS);        // 128 blocks
    edgenet_mlp_kernel<<<grid2, NTHREADS>>>(W1, b1, W2, b2, out);
}

// round 3
// speedup vs baseline: 2.4171x; 1.0171x over previous
#include <cuda_runtime.h>

// EdgeNet v3: node-split accum (float4 edge loads, streaming hints, 1-wave
// residency) + fast-math MLP epilogue kernel.

#define N_NODES 8192
#define N_EDGES 32768
#define S_SEG   16
#define NODES_PER_SEG (N_NODES / S_SEG)      // 512
#define E4      (N_EDGES / 4)                // 8192 float4 columns
#define A_THREADS 256
#define EGRPS   (E4 / A_THREADS)             // 32 edge-group blocks
#define NHID    100
#define M_THREADS 128

// Per (segment, edge): bo(float4), bi(float4).  16 MB.
__device__ float4 g_partial[(size_t)S_SEG * N_EDGES * 2];

__device__ __forceinline__ void fma4(float4& a, float s, const float4& x) {
    a.x = fmaf(s, x.x, a.x);
    a.y = fmaf(s, x.y, a.y);
    a.z = fmaf(s, x.z, a.z);
    a.w = fmaf(s, x.w, a.w);
}

__global__ __launch_bounds__(A_THREADS, 4)
void edgenet_accum_kernel(const float* __restrict__ X,
                          const float* __restrict__ Ri,
                          const float* __restrict__ Ro)
{
    __shared__ float4 sX[NODES_PER_SEG];   // 8 KB

    const int tid = threadIdx.x;
    const int seg = blockIdx.y;
    const int n0  = seg * NODES_PER_SEG;

    const float4* __restrict__ X4 = (const float4*)X;
    for (int i = tid; i < NODES_PER_SEG; i += A_THREADS)
        sX[i] = X4[n0 + i];
    __syncthreads();

    const int e4 = blockIdx.x * A_THREADS + tid;
    const float4* __restrict__ ro_p = (const float4*)Ro + (size_t)n0 * E4 + e4;
    const float4* __restrict__ ri_p = (const float4*)Ri + (size_t)n0 * E4 + e4;

    float4 ao0 = {0,0,0,0}, ao1 = {0,0,0,0}, ao2 = {0,0,0,0}, ao3 = {0,0,0,0};
    float4 ai0 = {0,0,0,0}, ai1 = {0,0,0,0}, ai2 = {0,0,0,0}, ai3 = {0,0,0,0};

    #pragma unroll 4
    for (int n = 0; n < NODES_PER_SEG; ++n) {
        const float4 ro = __ldcs(&ro_p[(size_t)n * E4]);   // stream-once: evict-first
        const float4 ri = __ldcs(&ri_p[(size_t)n * E4]);
        const float4 x  = sX[n];
        fma4(ao0, ro.x, x);  fma4(ao1, ro.y, x);
        fma4(ao2, ro.z, x);  fma4(ao3, ro.w, x);
        fma4(ai0, ri.x, x);  fma4(ai1, ri.y, x);
        fma4(ai2, ri.z, x);  fma4(ai3, ri.w, x);
    }

    float4* __restrict__ dst = &g_partial[((size_t)seg * N_EDGES + (size_t)e4 * 4) * 2];
    __stcs(&dst[0], ao0);  __stcs(&dst[1], ai0);
    __stcs(&dst[2], ao1);  __stcs(&dst[3], ai1);
    __stcs(&dst[4], ao2);  __stcs(&dst[5], ai2);
    __stcs(&dst[6], ao3);  __stcs(&dst[7], ai3);
}

__device__ __forceinline__ void add4(float4& a, const float4& b) {
    a.x += b.x; a.y += b.y; a.z += b.z; a.w += b.w;
}

__device__ __forceinline__ float fast_tanh(float x) {
    // tanh(x) = 1 - 2/(exp(2x)+1); saturates correctly at +/-inf.
    float e = __expf(2.0f * x);
    return 1.0f - __fdividef(2.0f, e + 1.0f);
}

__global__ __launch_bounds__(M_THREADS)
void edgenet_mlp_kernel(const float* __restrict__ W1,
                        const float* __restrict__ b1,
                        const float* __restrict__ W2,
                        const float* __restrict__ b2,
                        float* __restrict__ out)
{
    __shared__ __align__(16) float sW1t[NHID][8];   // W1 transposed [j][k]
    __shared__ float sb1[NHID];
    __shared__ float sW2[NHID];

    const int tid = threadIdx.x;
    for (int i = tid; i < 8 * NHID; i += M_THREADS) {
        int k = i / NHID, j = i % NHID;             // W1 is [8,100] row-major
        sW1t[j][k] = W1[i];
    }
    for (int i = tid; i < NHID; i += M_THREADS) {
        sb1[i] = b1[i];
        sW2[i] = W2[i];
    }
    __syncthreads();

    const int e = blockIdx.x * M_THREADS + tid;

    // Two independent accumulator pairs for ILP across the 16-seg reduction.
    float4 aoA = {0,0,0,0}, aiA = {0,0,0,0};
    float4 aoB = {0,0,0,0}, aiB = {0,0,0,0};
    #pragma unroll
    for (int seg = 0; seg < S_SEG; seg += 2) {
        const float4* pA = &g_partial[((size_t)seg * N_EDGES + e) * 2];
        const float4* pB = &g_partial[((size_t)(seg + 1) * N_EDGES + e) * 2];
        float4 a0 = __ldcs(&pA[0]), a1 = __ldcs(&pA[1]);
        float4 b0 = __ldcs(&pB[0]), b1v = __ldcs(&pB[1]);
        add4(aoA, a0);  add4(aiA, a1);
        add4(aoB, b0);  add4(aiB, b1v);
    }
    add4(aoA, aoB);
    add4(aiA, aiB);

    float acc = b2[0];
    #pragma unroll 4
    for (int j = 0; j < NHID; ++j) {
        const float4 w0 = *(const float4*)&sW1t[j][0];
        const float4 w1 = *(const float4*)&sW1t[j][4];
        float s = sb1[j];
        s = fmaf(aoA.x, w0.x, s);
        s = fmaf(aoA.y, w0.y, s);
        s = fmaf(aoA.z, w0.z, s);
        s = fmaf(aoA.w, w0.w, s);
        s = fmaf(aiA.x, w1.x, s);
        s = fmaf(aiA.y, w1.y, s);
        s = fmaf(aiA.z, w1.z, s);
        s = fmaf(aiA.w, w1.w, s);
        acc = fmaf(fast_tanh(s), sW2[j], acc);
    }
    out[e] = __fdividef(1.0f, 1.0f + __expf(-acc));
}

extern "C" void kernel_launch(void* const* d_in, const int* in_sizes, int n_in,
                              void* d_out, int out_size)
{
    // metadata order: X, Ri, Ro, W1, b1, W2, b2
    const float* X  = (const float*)d_in[0];
    const float* Ri = (const float*)d_in[1];
    const float* Ro = (const float*)d_in[2];
    const float* W1 = (const float*)d_in[3];
    const float* b1 = (const float*)d_in[4];
    const float* W2 = (const float*)d_in[5];
    const float* b2 = (const float*)d_in[6];
    float* out = (float*)d_out;

    dim3 grid1(EGRPS, S_SEG);              // 32 x 16 = 512 blocks (one wave @ 4/SM)
    edgenet_accum_kernel<<<grid1, A_THREADS>>>(X, Ri, Ro);

    dim3 grid2(N_EDGES / M_THREADS);       // 256 blocks
    edgenet_mlp_kernel<<<grid2, M_THREADS>>>(W1, b1, W2, b2, out);
}